// round 3
// baseline (speedup 1.0000x reference)
#include <cuda_runtime.h>
#include <math.h>

#define BATCH    4096
#define N_FEAT   256
#define HIDDEN   128
#define NTASK    1000
#define W1_ELEMS (N_FEAT * HIDDEN)   // 32768
#define SMAX     8                   // samples per W1 pass

// ---------------- scratch (allocation-free) ----------------
__device__ int g_offset[NTASK + 1];
__device__ int g_sorted[BATCH];

// ---------------- fused preprocessing: hist + scan + scatter ----------------
// Single block, 1024 threads. All state in smem.
__global__ __launch_bounds__(1024) void preproc_kernel(const int* __restrict__ task_ids) {
    __shared__ int hist[1024];
    __shared__ int offs[1024];
    __shared__ int cursor[1024];

    const int tid = threadIdx.x;
    hist[tid] = 0;
    cursor[tid] = 0;
    __syncthreads();

    #pragma unroll
    for (int i = tid; i < BATCH; i += 1024)
        atomicAdd(&hist[task_ids[i]], 1);
    __syncthreads();

    // inclusive Hillis-Steele scan over 1024 slots
    int own = hist[tid];
    for (int off = 1; off < 1024; off <<= 1) {
        const int v = (tid >= off) ? hist[tid - off] : 0;
        __syncthreads();
        hist[tid] += v;
        __syncthreads();
    }
    const int excl = hist[tid] - own;
    offs[tid] = excl;
    if (tid < NTASK) g_offset[tid] = excl;
    if (tid == NTASK - 1) g_offset[NTASK] = hist[tid];
    __syncthreads();

    #pragma unroll
    for (int i = tid; i < BATCH; i += 1024) {
        const int t = task_ids[i];
        const int pos = offs[t] + atomicAdd(&cursor[t], 1);
        g_sorted[pos] = i;
    }
}

// ---------------- packed f32x2 helpers (sm_100+) ----------------
__device__ __forceinline__ unsigned long long pack2(float v) {
    unsigned long long r;
    asm("mov.b64 %0, {%1, %1};" : "=l"(r) : "r"(__float_as_uint(v)));
    return r;
}
__device__ __forceinline__ void ffma2(unsigned long long& d,
                                      unsigned long long a,
                                      unsigned long long b) {
    asm("fma.rn.f32x2 %0, %1, %2, %0;" : "+l"(d) : "l"(a), "l"(b));
}

// ---------------- grouped MLP: one block per task ----------------
// 128 threads (4 warps). Warp w handles f in [64w,64w+64); lane owns hidden
// cols [4l,4l+4) as two f32x2 pairs. Up to SMAX samples share each W1 read.
__global__ __launch_bounds__(128) void task_mlp_grouped(
    const float* __restrict__ x,        // [B, 256]
    const float* __restrict__ l1_emb,   // [T, 256*128]
    const float* __restrict__ l1_bias,  // [T, 128]
    const float* __restrict__ l2_emb,   // [T, 128]
    const float* __restrict__ l2_bias,  // [T, 1]
    float*       __restrict__ out)      // [B, 1]
{
    const int t    = blockIdx.x;
    const int base = g_offset[t];
    const int n    = g_offset[t + 1] - base;
    if (n == 0) return;

    const int tid  = threadIdx.x;
    const int warp = tid >> 5;
    const int lane = tid & 31;

    // x rows pre-broadcast as (v,v) 64-bit pairs: inner loop = LDS.64 broadcast
    __shared__ __align__(16) unsigned long long xs_pk[SMAX][N_FEAT]; // 16 KB
    __shared__ __align__(16) float partial[4][SMAX][HIDDEN];         // 16 KB
    __shared__ float red[4][SMAX];
    __shared__ int   sidx[SMAX];

    const ulonglong2* __restrict__ w1q =
        (const ulonglong2*)(l1_emb + (long)t * W1_ELEMS);
    const float b1v = l1_bias[t * HIDDEN + tid];
    const float w2v = l2_emb[t * HIDDEN + tid];
    const float b2  = l2_bias[t];

    for (int c0 = 0; c0 < n; c0 += SMAX) {
        const int nc = min(SMAX, n - c0);

        if (tid < SMAX) sidx[tid] = (tid < nc) ? g_sorted[base + c0 + tid] : 0;
        __syncthreads();

        // Stage x rows, broadcast-packed; zero-pad past nc.
        for (int i = tid; i < SMAX * N_FEAT; i += 128) {
            const int s = i >> 8, f = i & 255;
            float v = 0.f;
            if (s < nc) v = x[(long)sidx[s] * N_FEAT + f];
            xs_pk[s][f] = pack2(v);
        }
        __syncthreads();

        // acc[s]: 4 hidden cols as 2 packed f32x2 pairs
        ulonglong2 acc[SMAX];
        #pragma unroll
        for (int s = 0; s < SMAX; ++s) { acc[s].x = 0ull; acc[s].y = 0ull; }

        const int f0 = warp * 64;
        #pragma unroll 4
        for (int ff = 0; ff < 64; ++ff) {
            const int f = f0 + ff;
            const ulonglong2 wv = w1q[f * (HIDDEN / 4) + lane]; // cols 4l..4l+3
            #pragma unroll
            for (int s = 0; s < SMAX; ++s) {
                const unsigned long long xp = xs_pk[s][f];      // (x,x)
                ffma2(acc[s].x, xp, wv.x);
                ffma2(acc[s].y, xp, wv.y);
            }
        }
        #pragma unroll
        for (int s = 0; s < SMAX; ++s)
            ((ulonglong2*)partial[warp][s])[lane] = acc[s];
        __syncthreads();

        // Epilogue: thread tid == hidden col
        #pragma unroll
        for (int s = 0; s < SMAX; ++s) {
            float h = partial[0][s][tid] + partial[1][s][tid]
                    + partial[2][s][tid] + partial[3][s][tid] + b1v;
            h = 0.5f * h * (1.0f + erff(h * 0.70710678118654752f)); // exact GELU
            float v = h * w2v;
            #pragma unroll
            for (int o = 16; o > 0; o >>= 1)
                v += __shfl_down_sync(0xffffffffu, v, o);
            if (lane == 0) red[warp][s] = v;
        }
        __syncthreads();
        if (tid < nc)
            out[sidx[tid]] = red[0][tid] + red[1][tid] + red[2][tid]
                           + red[3][tid] + b2;
        __syncthreads();   // protect xs_pk/sidx/red before next chunk
    }
}

extern "C" void kernel_launch(void* const* d_in, const int* in_sizes, int n_in,
                              void* d_out, int out_size) {
    const float* x        = (const float*)d_in[0];
    const int*   task_ids = (const int*)  d_in[1];
    const float* l1_emb   = (const float*)d_in[2];
    const float* l1_bias  = (const float*)d_in[3];
    const float* l2_emb   = (const float*)d_in[4];
    const float* l2_bias  = (const float*)d_in[5];
    float* out = (float*)d_out;

    preproc_kernel<<<1, 1024>>>(task_ids);
    task_mlp_grouped<<<NTASK, 128>>>(x, l1_emb, l1_bias, l2_emb, l2_bias, out);
}

// round 5
// speedup vs baseline: 1.3949x; 1.3949x over previous
#include <cuda_runtime.h>
#include <math.h>

#define BATCH    4096
#define N_FEAT   256
#define HIDDEN   128
#define NTASK    1000
#define W1_ELEMS (N_FEAT * HIDDEN)   // 32768
#define SMAX     4                   // samples per W1 pass (chunk 2+ hits L1/L2)

// ---------------- scratch (allocation-free) ----------------
__device__ int g_offset[NTASK + 1];
__device__ int g_sorted[BATCH];

// ---------------- fused preprocessing: hist + scan + scatter ----------------
__global__ __launch_bounds__(1024) void preproc_kernel(const int* __restrict__ task_ids) {
    __shared__ int hist[1024];
    __shared__ int offs[1024];
    __shared__ int cursor[1024];

    const int tid = threadIdx.x;
    hist[tid] = 0;
    cursor[tid] = 0;
    __syncthreads();

    #pragma unroll
    for (int i = tid; i < BATCH; i += 1024)
        atomicAdd(&hist[task_ids[i]], 1);
    __syncthreads();

    int own = hist[tid];
    for (int off = 1; off < 1024; off <<= 1) {
        const int v = (tid >= off) ? hist[tid - off] : 0;
        __syncthreads();
        hist[tid] += v;
        __syncthreads();
    }
    const int excl = hist[tid] - own;
    offs[tid] = excl;
    if (tid < NTASK) g_offset[tid] = excl;
    if (tid == NTASK - 1) g_offset[NTASK] = hist[tid];
    __syncthreads();

    #pragma unroll
    for (int i = tid; i < BATCH; i += 1024) {
        const int t = task_ids[i];
        const int pos = offs[t] + atomicAdd(&cursor[t], 1);
        g_sorted[pos] = i;
    }
}

// ---------------- packed f32x2 helpers (sm_100+) ----------------
__device__ __forceinline__ unsigned long long pack2(float v) {
    unsigned long long r;
    asm("mov.b64 %0, {%1, %1};" : "=l"(r) : "r"(__float_as_uint(v)));
    return r;
}
__device__ __forceinline__ void ffma2(unsigned long long& d,
                                      unsigned long long a,
                                      unsigned long long b) {
    asm("fma.rn.f32x2 %0, %1, %2, %0;" : "+l"(d) : "l"(a), "l"(b));
}

// ---------------- grouped MLP: one block per task ----------------
// 128 threads, 4 warps. Warp w handles f in [64w, 64w+64); lane owns hidden
// cols [4l, 4l+4) as two f32x2 pairs. SMAX samples share each W1 read.
// W1 streamed in 8-wide load batches (MLP=8).
__global__ __launch_bounds__(128, 7) void task_mlp_grouped(
    const float* __restrict__ x,        // [B, 256]
    const float* __restrict__ l1_emb,   // [T, 256*128]
    const float* __restrict__ l1_bias,  // [T, 128]
    const float* __restrict__ l2_emb,   // [T, 128]
    const float* __restrict__ l2_bias,  // [T, 1]
    float*       __restrict__ out)      // [B, 1]
{
    const int t    = blockIdx.x;
    const int base = g_offset[t];
    const int n    = g_offset[t + 1] - base;
    if (n == 0) return;

    const int tid  = threadIdx.x;
    const int warp = tid >> 5;
    const int lane = tid & 31;

    __shared__ __align__(16) unsigned long long xs_pk[SMAX][N_FEAT]; // 8 KB
    __shared__ __align__(16) float partial[4][SMAX][HIDDEN];         // 8 KB
    __shared__ float red[4][SMAX];
    __shared__ int   sidx[SMAX];

    const ulonglong2* __restrict__ w1q =
        (const ulonglong2*)(l1_emb + (long)t * W1_ELEMS);
    const float b1v = l1_bias[t * HIDDEN + tid];
    const float w2v = l2_emb[t * HIDDEN + tid];
    const float b2  = l2_bias[t];

    for (int c0 = 0; c0 < n; c0 += SMAX) {
        const int nc = min(SMAX, n - c0);

        if (tid < SMAX) sidx[tid] = (tid < nc) ? g_sorted[base + c0 + tid] : 0;
        __syncthreads();

        // Stage x rows, broadcast-packed (v,v); zero-pad past nc.
        for (int i = tid; i < SMAX * N_FEAT; i += 128) {
            const int s = i >> 8, f = i & 255;
            float v = 0.f;
            if (s < nc) v = x[(long)sidx[s] * N_FEAT + f];
            xs_pk[s][f] = pack2(v);
        }
        __syncthreads();

        ulonglong2 acc[SMAX];
        #pragma unroll
        for (int s = 0; s < SMAX; ++s) { acc[s].x = 0ull; acc[s].y = 0ull; }

        const int f0 = warp * 64;
        #pragma unroll 1
        for (int fb = 0; fb < 8; ++fb) {          // 8 batches of 8 f's
            const int fbase = f0 + fb * 8;
            ulonglong2 wv[8];                     // 8 outstanding LDG.128
            #pragma unroll
            for (int j = 0; j < 8; ++j)
                wv[j] = w1q[(fbase + j) * (HIDDEN / 4) + lane];
            #pragma unroll
            for (int j = 0; j < 8; ++j) {
                const int f = fbase + j;
                #pragma unroll
                for (int s = 0; s < SMAX; ++s) {
                    const unsigned long long xp = xs_pk[s][f];  // (x,x)
                    ffma2(acc[s].x, xp, wv[j].x);
                    ffma2(acc[s].y, xp, wv[j].y);
                }
            }
        }
        #pragma unroll
        for (int s = 0; s < SMAX; ++s)
            ((ulonglong2*)partial[warp][s])[lane] = acc[s];
        __syncthreads();

        // Epilogue: thread tid == hidden col
        #pragma unroll
        for (int s = 0; s < SMAX; ++s) {
            float h = partial[0][s][tid] + partial[1][s][tid]
                    + partial[2][s][tid] + partial[3][s][tid] + b1v;
            h = 0.5f * h * (1.0f + erff(h * 0.70710678118654752f)); // exact GELU
            float v = h * w2v;
            #pragma unroll
            for (int o = 16; o > 0; o >>= 1)
                v += __shfl_down_sync(0xffffffffu, v, o);
            if (lane == 0) red[warp][s] = v;
        }
        __syncthreads();
        if (tid < nc)
            out[sidx[tid]] = red[0][tid] + red[1][tid] + red[2][tid]
                           + red[3][tid] + b2;
        __syncthreads();   // protect xs_pk/sidx/red before next chunk
    }
}

extern "C" void kernel_launch(void* const* d_in, const int* in_sizes, int n_in,
                              void* d_out, int out_size) {
    const float* x        = (const float*)d_in[0];
    const int*   task_ids = (const int*)  d_in[1];
    const float* l1_emb   = (const float*)d_in[2];
    const float* l1_bias  = (const float*)d_in[3];
    const float* l2_emb   = (const float*)d_in[4];
    const float* l2_bias  = (const float*)d_in[5];
    float* out = (float*)d_out;

    preproc_kernel<<<1, 1024>>>(task_ids);
    task_mlp_grouped<<<NTASK, 128>>>(x, l1_emb, l1_bias, l2_emb, l2_bias, out);
}